// round 11
// baseline (speedup 1.0000x reference)
#include <cuda_runtime.h>
#include <cstdint>

// Shift op: x[32,64,56,56] -> out[32,576,56,56]
// out[n, c*9 + s, y, x] = x[n, c, y + s/3 - 1, x + s%3 - 1], zero-padded.
//
// R11: 4 output rows per thread (H=56 = 14 row-quads).
//  - 6 aligned float4 row loads (y-1..y+4) + 12 edge scalars = 18 LDG
//    feeding 36 STG.128 (0.5 loads/store; R4 was 0.67).
//  - index decomposition amortized 4x.
//  - evict-last policy loads, .cs evict-first stores (as R7).

#define N_  32
#define C_  64
#define H_  56
#define W_  56
#define W4 (W_ / 4)      // 14
#define H4 (H_ / 4)      // 14 row-quads

__device__ __forceinline__ uint64_t mk_policy() {
    uint64_t p;
    asm("createpolicy.fractional.L2::evict_last.b64 %0, 1.0;" : "=l"(p));
    return p;
}
__device__ __forceinline__ float4 ldg_el4(const float* p, uint64_t pol) {
    float4 v;
    asm volatile("ld.global.nc.L2::cache_hint.v4.f32 {%0,%1,%2,%3}, [%4], %5;"
                 : "=f"(v.x), "=f"(v.y), "=f"(v.z), "=f"(v.w)
                 : "l"(p), "l"(pol));
    return v;
}
__device__ __forceinline__ float ldg_el1(const float* p, uint64_t pol) {
    float v;
    asm volatile("ld.global.nc.L2::cache_hint.f32 %0, [%1], %2;"
                 : "=f"(v) : "l"(p), "l"(pol));
    return v;
}

__global__ __launch_bounds__(256) void shift_kernel(
    const float* __restrict__ in, float* __restrict__ out, int total)
{
    int idx = blockIdx.x * blockDim.x + threadIdx.x;
    if (idx >= total) return;

    const uint64_t pol = mk_policy();

    // idx -> (nc, yq, x4);  y = 4*yq
    int x4 = idx % W4;
    int t  = idx / W4;
    int yq = t % H4;
    int nc = t / H4;
    int y  = yq * 4;

    int x0 = x4 * 4;
    const float* plane = in + (long long)nc * (H_ * W_);

    // rows y-1 .. y+4 (6 rows)
    float4 v[6];
    float  lft[6], rgt[6];
    #pragma unroll
    for (int r = 0; r < 6; r++) {
        int sy = y + r - 1;
        if ((unsigned)sy < (unsigned)H_) {
            const float* row = plane + sy * W_;
            v[r]   = ldg_el4(row + x0, pol);
            lft[r] = (x0 > 0)      ? ldg_el1(row + x0 - 1, pol) : 0.f;
            rgt[r] = (x0 + 4 < W_) ? ldg_el1(row + x0 + 4, pol) : 0.f;
        } else {
            v[r]   = make_float4(0.f, 0.f, 0.f, 0.f);
            lft[r] = 0.f;
            rgt[r] = 0.f;
        }
    }

    // out float4 base for (nc, s=0, y, x4)
    float4* obase = reinterpret_cast<float4*>(out)
                    + ((long long)nc * 9) * (H_ * W4) + y * W4 + x4;
    const int sstride = H_ * W4;   // one s-plane in float4s

    #pragma unroll
    for (int dy = 0; dy < 3; dy++) {
        #pragma unroll
        for (int r = 0; r < 4; r++) {
            float4 b = v[dy + r];                               // src row y+r+dy-1
            float4 a = make_float4(lft[dy + r], b.x, b.y, b.z); // dx = 0
            float4 c = make_float4(b.y, b.z, b.w, rgt[dy + r]); // dx = 2
            float4* o = obase + r * W4;
            __stcs(o + (dy * 3 + 0) * sstride, a);
            __stcs(o + (dy * 3 + 1) * sstride, b);
            __stcs(o + (dy * 3 + 2) * sstride, c);
        }
    }
}

extern "C" void kernel_launch(void* const* d_in, const int* in_sizes, int n_in,
                              void* d_out, int out_size) {
    const float* x = (const float*)d_in[0];
    float* out = (float*)d_out;
    int total = N_ * C_ * H4 * W4;   // 401,408 threads
    int threads = 256;
    int blocks = (total + threads - 1) / threads;
    shift_kernel<<<blocks, threads>>>(x, out, total);
}

// round 12
// speedup vs baseline: 1.2029x; 1.2029x over previous
#include <cuda_runtime.h>
#include <cstdint>

// Shift op: x[32,64,56,56] -> out[32,576,56,56]
// out[n, c*9 + s, y, x] = x[n, c, y + s/3 - 1, x + s%3 - 1], zero-padded.
//
// R12 = R3 (SMEM staging + cp.async.bulk stores) with DOUBLE BUFFERING:
// each block does two y-tiles; tile0's bulk drain overlaps tile1's compute,
// and the mandatory wait_group 0 happens once at block exit (2x amortized).
//
// Block = 128 threads; compute uses 112 (8 rows x 14 float4), drain uses 9.
// Tile = 9 s-planes x 8 rows x 224B = 16128B; two buffers = 32256B SMEM.

#define N_  32
#define C_  64
#define H_  56
#define W_  56
#define W4 (W_ / 4)          // 14
#define BY  8                // rows per tile
#define NT_Y (H_ / BY)       // 7 y-tiles
#define NPAIR ((NT_Y + 1) / 2)   // 4 tile-pairs per nc
#define TILE_V4 (9 * BY * W4)    // 1008 float4 = 16128 B

__global__ __launch_bounds__(128) void shift_kernel(
    const float* __restrict__ in, float* __restrict__ out)
{
    __shared__ float4 tile[2][TILE_V4];   // 32256 B

    const int tid = threadIdx.x;
    const int nc   = blockIdx.x / NPAIR;
    const int pair = blockIdx.x % NPAIR;
    const float* plane = in + (long long)nc * (H_ * W_);

    #pragma unroll
    for (int i = 0; i < 2; i++) {
        const int yt = pair * 2 + i;
        if (yt >= NT_Y) break;
        const int y0 = yt * BY;

        if (tid < BY * W4) {
            const int ty = tid / W4;
            const int x4 = tid % W4;
            const int y  = y0 + ty;
            const int x0 = x4 * 4;

            float4 v[3];
            float  lft[3], rgt[3];
            #pragma unroll
            for (int dy = 0; dy < 3; dy++) {
                int sy = y + dy - 1;
                if ((unsigned)sy < (unsigned)H_) {
                    const float* row = plane + sy * W_;
                    v[dy]   = *reinterpret_cast<const float4*>(row + x0);
                    lft[dy] = (x0 > 0)      ? __ldg(row + x0 - 1) : 0.f;
                    rgt[dy] = (x0 + 4 < W_) ? __ldg(row + x0 + 4) : 0.f;
                } else {
                    v[dy]   = make_float4(0.f, 0.f, 0.f, 0.f);
                    lft[dy] = 0.f;
                    rgt[dy] = 0.f;
                }
            }

            #pragma unroll
            for (int dy = 0; dy < 3; dy++) {
                float4 b = v[dy];
                float4 a = make_float4(lft[dy], b.x, b.y, b.z);   // dx = 0
                float4 c = make_float4(b.y, b.z, b.w, rgt[dy]);   // dx = 2
                tile[i][((dy * 3 + 0) * BY + ty) * W4 + x4] = a;
                tile[i][((dy * 3 + 1) * BY + ty) * W4 + x4] = b;
                tile[i][((dy * 3 + 2) * BY + ty) * W4 + x4] = c;
            }
        }

        __syncthreads();

        // 9 threads drain one s-plane chunk each (1792 contiguous bytes),
        // committed but NOT waited — drain overlaps next tile's compute.
        if (tid < 9) {
            const int s = tid;
            asm volatile("fence.proxy.async.shared::cta;" ::: "memory");
            uint32_t saddr = (uint32_t)__cvta_generic_to_shared(
                reinterpret_cast<const char*>(tile[i]) + s * (BY * W_ * 4));
            const float* gdst = out + ((long long)(nc * 9 + s) * H_ + y0) * W_;
            asm volatile(
                "cp.async.bulk.global.shared::cta.bulk_group [%0], [%1], %2;"
                :: "l"(gdst), "r"(saddr), "r"(BY * W_ * 4)
                : "memory");
            asm volatile("cp.async.bulk.commit_group;" ::: "memory");
        }
        // no barrier needed before next compute: it writes tile[i^1] only
    }

    // SMEM must outlive the bulk reads: single wait at block exit.
    if (tid < 9) {
        asm volatile("cp.async.bulk.wait_group 0;" ::: "memory");
    }
}

extern "C" void kernel_launch(void* const* d_in, const int* in_sizes, int n_in,
                              void* d_out, int out_size) {
    const float* x = (const float*)d_in[0];
    float* out = (float*)d_out;
    int blocks = N_ * C_ * NPAIR;   // 2048 * 4 = 8192
    shift_kernel<<<blocks, 128>>>(x, out);
}